// round 10
// baseline (speedup 1.0000x reference)
#include <cuda_runtime.h>
#include <cuda_bf16.h>
#include <cstdint>

#define DINLINE __device__ __forceinline__

// ---------------- scratch (device globals; no runtime allocation) ----------
__device__ float g_partial[256];
__device__ float g_scales[4096];
__device__ float g_alpha_out;
__device__ __align__(128) __nv_bfloat16 g_wqh[16777216];  // W ternary bf16 [N,K]
__device__ __align__(128) __nv_bfloat16 g_xqh[16777216];  // x quant  bf16 [M,K]

// ---------------- PTX helpers (baseline ISA only) ---------------------------
DINLINE uint32_t smem_u32(const void* p) {
    uint32_t a;
    asm("{ .reg .u64 t; cvta.to.shared.u64 t, %1; cvt.u32.u64 %0, t; }"
        : "=r"(a) : "l"(p));
    return a;
}
DINLINE void cp16(uint32_t dst, const void* src) {
    asm volatile("cp.async.cg.shared.global [%0], [%1], 16;" :: "r"(dst), "l"(src));
}
DINLINE void cp_commit() { asm volatile("cp.async.commit_group;" ::: "memory"); }
DINLINE void cp_wait1()  { asm volatile("cp.async.wait_group 1;" ::: "memory"); }

DINLINE void ldsm_x4(uint32_t& r0, uint32_t& r1, uint32_t& r2, uint32_t& r3, uint32_t addr) {
    asm volatile("ldmatrix.sync.aligned.m8n8.x4.shared.b16 {%0,%1,%2,%3}, [%4];"
                 : "=r"(r0), "=r"(r1), "=r"(r2), "=r"(r3) : "r"(addr));
}
DINLINE void mma_bf16(float* c, uint32_t a0, uint32_t a1, uint32_t a2, uint32_t a3,
                      uint32_t b0, uint32_t b1) {
    asm volatile(
        "mma.sync.aligned.m16n8k16.row.col.f32.bf16.bf16.f32 "
        "{%0,%1,%2,%3}, {%4,%5,%6,%7}, {%8,%9}, {%0,%1,%2,%3};"
        : "+f"(c[0]), "+f"(c[1]), "+f"(c[2]), "+f"(c[3])
        : "r"(a0), "r"(a1), "r"(a2), "r"(a3), "r"(b0), "r"(b1));
}
DINLINE int clampi(int v, int lo, int hi) { return v < lo ? lo : (v > hi ? hi : v); }
DINLINE uint32_t pack_bf16(float a, float b) {
    __nv_bfloat162 h;
    h.x = __float2bfloat16(a);
    h.y = __float2bfloat16(b);
    return *reinterpret_cast<uint32_t*>(&h);
}

// ---------------- kernel 1: |W| partial sums ---------------------------------
__global__ void __launch_bounds__(256) k_abs_partial(const float4* __restrict__ w) {
    __shared__ float red[256];
    const int b = blockIdx.x, t = threadIdx.x;
    const float4* p = w + (size_t)b * 16384;
    float s = 0.f;
#pragma unroll 8
    for (int i = 0; i < 64; i++) {
        float4 v = p[t + 256 * i];
        s += fabsf(v.x) + fabsf(v.y) + fabsf(v.z) + fabsf(v.w);
    }
    red[t] = s; __syncthreads();
#pragma unroll
    for (int o = 128; o > 0; o >>= 1) { if (t < o) red[t] += red[t + o]; __syncthreads(); }
    if (t == 0) g_partial[b] = red[0];
}

// ---------------- kernel 2: finalize alpha + ternary quantize W -> bf16 -----
__global__ void __launch_bounds__(256) k_quant_w(const float4* __restrict__ w) {
    __shared__ float red[256];
    const int t = threadIdx.x;
    red[t] = g_partial[t]; __syncthreads();
#pragma unroll
    for (int o = 128; o > 0; o >>= 1) { if (t < o) red[t] += red[t + o]; __syncthreads(); }
    const float alpha = fmaxf(red[0] * (1.0f / 16777216.0f), 1e-10f);
    if (blockIdx.x == 0 && t == 0) g_alpha_out = alpha;
    const float inv_alpha = 1.0f / alpha;

    const int idx = blockIdx.x * 256 + t;          // float4 index, 4194304 total
    float4 v = w[idx];
    int q0 = clampi(__float2int_rn(v.x * inv_alpha), -1, 1);
    int q1 = clampi(__float2int_rn(v.y * inv_alpha), -1, 1);
    int q2 = clampi(__float2int_rn(v.z * inv_alpha), -1, 1);
    int q3 = clampi(__float2int_rn(v.w * inv_alpha), -1, 1);
    uint2 h;
    h.x = pack_bf16((float)q0, (float)q1);
    h.y = pack_bf16((float)q2, (float)q3);
    reinterpret_cast<uint2*>(g_wqh)[idx] = h;
}

// ---------------- kernel 3: RMSNorm + int8-grid quantize x -> bf16 ----------
__global__ void __launch_bounds__(256) k_quant_x(const float* __restrict__ x,
                                                 const float* __restrict__ nw) {
    __shared__ float red[256];
    const int m = blockIdx.x, t = threadIdx.x;
    const float4* xr = reinterpret_cast<const float4*>(x + (size_t)m * 4096);
    const float4* nwr = reinterpret_cast<const float4*>(nw);

    float4 v[4], g[4];
    float ss = 0.f;
#pragma unroll
    for (int i = 0; i < 4; i++) {
        v[i] = xr[t + 256 * i];
        g[i] = nwr[t + 256 * i];
        ss += v[i].x * v[i].x + v[i].y * v[i].y + v[i].z * v[i].z + v[i].w * v[i].w;
    }
    red[t] = ss; __syncthreads();
#pragma unroll
    for (int o = 128; o > 0; o >>= 1) { if (t < o) red[t] += red[t + o]; __syncthreads(); }
    const float rinv = 1.0f / sqrtf(red[0] * (1.0f / 4096.0f) + 1e-6f);
    __syncthreads();

    float mx = 0.f;
#pragma unroll
    for (int i = 0; i < 4; i++) {
        v[i].x *= rinv * g[i].x; v[i].y *= rinv * g[i].y;
        v[i].z *= rinv * g[i].z; v[i].w *= rinv * g[i].w;
        mx = fmaxf(mx, fmaxf(fmaxf(fabsf(v[i].x), fabsf(v[i].y)),
                             fmaxf(fabsf(v[i].z), fabsf(v[i].w))));
    }
    red[t] = mx; __syncthreads();
#pragma unroll
    for (int o = 128; o > 0; o >>= 1) { if (t < o) red[t] = fmaxf(red[t], red[t + o]); __syncthreads(); }
    const float gamma = fmaxf(red[0], 1e-10f);
    if (t == 0) g_scales[m] = g_alpha_out * gamma * (1.0f / 127.0f);
    const float qs = 127.0f / gamma;
    uint2* dsth = reinterpret_cast<uint2*>(g_xqh) + (size_t)m * 1024;
#pragma unroll
    for (int i = 0; i < 4; i++) {
        int q0 = clampi(__float2int_rn(v[i].x * qs), -128, 127);
        int q1 = clampi(__float2int_rn(v[i].y * qs), -128, 127);
        int q2 = clampi(__float2int_rn(v[i].z * qs), -128, 127);
        int q3 = clampi(__float2int_rn(v[i].w * qs), -128, 127);
        uint2 h;
        h.x = pack_bf16((float)q0, (float)q1);
        h.y = pack_bf16((float)q2, (float)q3);
        dsth[t + 256 * i] = h;
    }
}

// ================= bf16 HMMA GEMM (full M) + per-row rescale ================
// D[m,n] = sum_k xq[m,k] * wq[n,k]  (exact: integers in bf16, fp32 accum)
// CTA tile 128x128, BK=128 bf16 (256B rows -> only 32 sync points),
// pad-272 smem (272 mod 128 == 16: same conflict-free ldsm pattern as pad-144),
// 3-stage cp.async pipeline, 8 warps of 64x32, 1 CTA/SM,
// fragment double-buffering across the 8 k16 sub-chunks of each stage.
static constexpr int BKH     = 128;                  // bf16 elems per chunk
static constexpr int ROWB    = BKH * 2;              // 256 bytes per row
static constexpr int LDS_PADH = 272;                 // row stride in smem
static constexpr int ASIZEH  = 128 * LDS_PADH;       // 34816
static constexpr int STAGEH  = 2 * ASIZEH;           // 69632
static constexpr int SMEMH   = 3 * STAGEH;           // 208896

__global__ void __launch_bounds__(256, 1) k_gemm_bf16(float* __restrict__ out) {
    extern __shared__ char smemraw[];
    const uint32_t sbase = smem_u32(smemraw);
    const int t = threadIdx.x;
    const int lane = t & 31, wid = t >> 5;
    const int warpM = wid >> 2, warpN = wid & 3;
    const int m0 = blockIdx.y * 128, n0 = blockIdx.x * 128;

    const char* gA = reinterpret_cast<const char*>(g_xqh) + (size_t)m0 * 8192;
    const char* gB = reinterpret_cast<const char*>(g_wqh) + (size_t)n0 * 8192;

    // loader: 2 threads per 256B row; 8x cp16 each, for A and for B
    const int lr = t >> 1;              // 0..127
    const int lc = (t & 1) * 128;       // 0 or 128
    const char* pA = gA + (size_t)lr * 8192 + lc;
    const char* pB = gB + (size_t)lr * 8192 + lc;
    const uint32_t offA = (uint32_t)(lr * LDS_PADH + lc);
    const uint32_t offB = offA + ASIZEH;

    const int xrow = (lane & 7) + ((lane >> 3) & 1) * 8;
    const int xcol = (lane >> 4) * 16;
    const uint32_t baseA = (uint32_t)((warpM * 64 + xrow) * LDS_PADH + xcol);
    const uint32_t baseB = (uint32_t)(ASIZEH + (warpN * 32 + xrow) * LDS_PADH + xcol);

    float acc[4][4][4];
#pragma unroll
    for (int i = 0; i < 4; i++)
#pragma unroll
        for (int j = 0; j < 4; j++)
#pragma unroll
            for (int q = 0; q < 4; q++) acc[i][j][q] = 0.f;

    auto load_stage = [&](int s, int c) {
        const uint32_t dst = sbase + s * STAGEH;
        const char* sA = pA + (size_t)c * ROWB;
        const char* sB = pB + (size_t)c * ROWB;
#pragma unroll
        for (int i = 0; i < 8; i++) {
            cp16(dst + offA + i * 16, sA + i * 16);
            cp16(dst + offB + i * 16, sB + i * 16);
        }
    };

    // fragment double buffers
    uint32_t a[2][4][4];
    uint32_t b[2][4][2];

    auto load_frags = [&](int buf, uint32_t st, int kk) {
#pragma unroll
        for (int i = 0; i < 4; i++)
            ldsm_x4(a[buf][i][0], a[buf][i][1], a[buf][i][2], a[buf][i][3],
                    st + baseA + i * (16 * LDS_PADH) + kk * 32);
#pragma unroll
        for (int j2 = 0; j2 < 2; j2++) {
            uint32_t q0, q1, q2, q3;
            ldsm_x4(q0, q1, q2, q3,
                    st + baseB + j2 * (16 * LDS_PADH) + kk * 32);
            b[buf][2 * j2][0] = q0; b[buf][2 * j2 + 1][0] = q1;
            b[buf][2 * j2][1] = q2; b[buf][2 * j2 + 1][1] = q3;
        }
    };

    // prologue: fill stages 0,1 (groups 0,1)
#pragma unroll
    for (int c = 0; c < 2; c++) { load_stage(c, c); cp_commit(); }

    for (int c = 0; c < 32; c++) {
        // At top of chunk c: pending groups are for stages c, c+1.
        // wait_group 1 -> stage c complete; barrier -> visible to all threads.
        // Stage (c+2)%3 == (c-1)%3: its readers finished during chunk c-1,
        // strictly before this barrier, so refilling it is safe.
        cp_wait1();
        __syncthreads();

        const int cn = c + 2;
        if (cn < 32) load_stage(cn % 3, cn);
        cp_commit();                 // uniform group count

        const uint32_t stC = sbase + (c % 3) * STAGEH;
        load_frags(0, stC, 0);       // only non-overlapped frag load (1 of 8)

#pragma unroll
        for (int kk = 0; kk < 8; kk++) {
            const int cur = kk & 1;
            if (kk < 7) load_frags(cur ^ 1, stC, kk + 1);  // overlaps MMAs below
#pragma unroll
            for (int i = 0; i < 4; i++)
#pragma unroll
                for (int j = 0; j < 4; j++)
                    mma_bf16(acc[i][j], a[cur][i][0], a[cur][i][1],
                             a[cur][i][2], a[cur][i][3],
                             b[cur][j][0], b[cur][j][1]);
        }
    }

    // epilogue: scale by per-row alpha*gamma/127 and store fp32
    const int rq = lane >> 2;
    const int cq = (lane & 3) * 2;
    const int nw = n0 + warpN * 32 + cq;
#pragma unroll
    for (int i = 0; i < 4; i++) {
        const int row = m0 + warpM * 64 + i * 16 + rq;
        const float s0 = g_scales[row];
        const float s1 = g_scales[row + 8];
        float* o0 = out + (size_t)row * 4096 + nw;
        float* o1 = o0 + (size_t)8 * 4096;
#pragma unroll
        for (int j = 0; j < 4; j++) {
            float2 v0; v0.x = acc[i][j][0] * s0; v0.y = acc[i][j][1] * s0;
            *reinterpret_cast<float2*>(o0 + j * 8) = v0;
            float2 v1; v1.x = acc[i][j][2] * s1; v1.y = acc[i][j][3] * s1;
            *reinterpret_cast<float2*>(o1 + j * 8) = v1;
        }
    }
}

// ---------------- launch -----------------------------------------------------
extern "C" void kernel_launch(void* const* d_in, const int* in_sizes, int n_in,
                              void* d_out, int out_size) {
    (void)in_sizes; (void)n_in; (void)out_size;
    const float* x  = reinterpret_cast<const float*>(d_in[0]);
    const float* w  = reinterpret_cast<const float*>(d_in[1]);
    const float* nw = reinterpret_cast<const float*>(d_in[2]);
    float* y = reinterpret_cast<float*>(d_out);

    static bool attr_set = false;
    if (!attr_set) {
        cudaFuncSetAttribute(k_gemm_bf16, cudaFuncAttributeMaxDynamicSharedMemorySize, SMEMH);
        attr_set = true;
    }

    k_abs_partial<<<256, 256>>>(reinterpret_cast<const float4*>(w));
    k_quant_w<<<16384, 256>>>(reinterpret_cast<const float4*>(w));
    k_quant_x<<<4096, 256>>>(x, nw);
    k_gemm_bf16<<<dim3(32, 32), 256, SMEMH>>>(y);
}

// round 11
// speedup vs baseline: 1.3393x; 1.3393x over previous
#include <cuda_runtime.h>
#include <cuda_bf16.h>
#include <cstdint>

#define DINLINE __device__ __forceinline__

// ---------------- scratch (device globals; no runtime allocation) ----------
__device__ float g_partial[256];
__device__ float g_scales[4096];
__device__ float g_alpha_out;
__device__ __align__(128) __nv_bfloat16 g_wqh[16777216];  // W ternary bf16 [N,K]
__device__ __align__(128) __nv_bfloat16 g_xqh[16777216];  // x quant  bf16 [M,K]

// ---------------- PTX helpers (baseline ISA only) ---------------------------
DINLINE uint32_t smem_u32(const void* p) {
    uint32_t a;
    asm("{ .reg .u64 t; cvta.to.shared.u64 t, %1; cvt.u32.u64 %0, t; }"
        : "=r"(a) : "l"(p));
    return a;
}
DINLINE void cp16(uint32_t dst, const void* src) {
    asm volatile("cp.async.cg.shared.global [%0], [%1], 16;" :: "r"(dst), "l"(src));
}
DINLINE void cp_commit() { asm volatile("cp.async.commit_group;" ::: "memory"); }
DINLINE void cp_wait1()  { asm volatile("cp.async.wait_group 1;" ::: "memory"); }

DINLINE void ldsm_x4(uint32_t& r0, uint32_t& r1, uint32_t& r2, uint32_t& r3, uint32_t addr) {
    asm volatile("ldmatrix.sync.aligned.m8n8.x4.shared.b16 {%0,%1,%2,%3}, [%4];"
                 : "=r"(r0), "=r"(r1), "=r"(r2), "=r"(r3) : "r"(addr));
}
DINLINE void mma_bf16(float* c, uint32_t a0, uint32_t a1, uint32_t a2, uint32_t a3,
                      uint32_t b0, uint32_t b1) {
    asm volatile(
        "mma.sync.aligned.m16n8k16.row.col.f32.bf16.bf16.f32 "
        "{%0,%1,%2,%3}, {%4,%5,%6,%7}, {%8,%9}, {%0,%1,%2,%3};"
        : "+f"(c[0]), "+f"(c[1]), "+f"(c[2]), "+f"(c[3])
        : "r"(a0), "r"(a1), "r"(a2), "r"(a3), "r"(b0), "r"(b1));
}
DINLINE int clampi(int v, int lo, int hi) { return v < lo ? lo : (v > hi ? hi : v); }
DINLINE uint32_t pack_bf16(float a, float b) {
    __nv_bfloat162 h;
    h.x = __float2bfloat16(a);
    h.y = __float2bfloat16(b);
    return *reinterpret_cast<uint32_t*>(&h);
}

// ---------------- kernel 1: |W| partial sums ---------------------------------
__global__ void __launch_bounds__(256) k_abs_partial(const float4* __restrict__ w) {
    __shared__ float red[256];
    const int b = blockIdx.x, t = threadIdx.x;
    const float4* p = w + (size_t)b * 16384;
    float s = 0.f;
#pragma unroll 8
    for (int i = 0; i < 64; i++) {
        float4 v = p[t + 256 * i];
        s += fabsf(v.x) + fabsf(v.y) + fabsf(v.z) + fabsf(v.w);
    }
    red[t] = s; __syncthreads();
#pragma unroll
    for (int o = 128; o > 0; o >>= 1) { if (t < o) red[t] += red[t + o]; __syncthreads(); }
    if (t == 0) g_partial[b] = red[0];
}

// ---------------- kernel 2: finalize alpha + ternary quantize W -> bf16 -----
__global__ void __launch_bounds__(256) k_quant_w(const float4* __restrict__ w) {
    __shared__ float red[256];
    const int t = threadIdx.x;
    red[t] = g_partial[t]; __syncthreads();
#pragma unroll
    for (int o = 128; o > 0; o >>= 1) { if (t < o) red[t] += red[t + o]; __syncthreads(); }
    const float alpha = fmaxf(red[0] * (1.0f / 16777216.0f), 1e-10f);
    if (blockIdx.x == 0 && t == 0) g_alpha_out = alpha;
    const float inv_alpha = 1.0f / alpha;

    const int idx = blockIdx.x * 256 + t;          // float4 index, 4194304 total
    float4 v = w[idx];
    int q0 = clampi(__float2int_rn(v.x * inv_alpha), -1, 1);
    int q1 = clampi(__float2int_rn(v.y * inv_alpha), -1, 1);
    int q2 = clampi(__float2int_rn(v.z * inv_alpha), -1, 1);
    int q3 = clampi(__float2int_rn(v.w * inv_alpha), -1, 1);
    uint2 h;
    h.x = pack_bf16((float)q0, (float)q1);
    h.y = pack_bf16((float)q2, (float)q3);
    reinterpret_cast<uint2*>(g_wqh)[idx] = h;
}

// ---------------- kernel 3: RMSNorm + int8-grid quantize x -> bf16 ----------
__global__ void __launch_bounds__(256) k_quant_x(const float* __restrict__ x,
                                                 const float* __restrict__ nw) {
    __shared__ float red[256];
    const int m = blockIdx.x, t = threadIdx.x;
    const float4* xr = reinterpret_cast<const float4*>(x + (size_t)m * 4096);
    const float4* nwr = reinterpret_cast<const float4*>(nw);

    float4 v[4], g[4];
    float ss = 0.f;
#pragma unroll
    for (int i = 0; i < 4; i++) {
        v[i] = xr[t + 256 * i];
        g[i] = nwr[t + 256 * i];
        ss += v[i].x * v[i].x + v[i].y * v[i].y + v[i].z * v[i].z + v[i].w * v[i].w;
    }
    red[t] = ss; __syncthreads();
#pragma unroll
    for (int o = 128; o > 0; o >>= 1) { if (t < o) red[t] += red[t + o]; __syncthreads(); }
    const float rinv = 1.0f / sqrtf(red[0] * (1.0f / 4096.0f) + 1e-6f);
    __syncthreads();

    float mx = 0.f;
#pragma unroll
    for (int i = 0; i < 4; i++) {
        v[i].x *= rinv * g[i].x; v[i].y *= rinv * g[i].y;
        v[i].z *= rinv * g[i].z; v[i].w *= rinv * g[i].w;
        mx = fmaxf(mx, fmaxf(fmaxf(fabsf(v[i].x), fabsf(v[i].y)),
                             fmaxf(fabsf(v[i].z), fabsf(v[i].w))));
    }
    red[t] = mx; __syncthreads();
#pragma unroll
    for (int o = 128; o > 0; o >>= 1) { if (t < o) red[t] = fmaxf(red[t], red[t + o]); __syncthreads(); }
    const float gamma = fmaxf(red[0], 1e-10f);
    if (t == 0) g_scales[m] = g_alpha_out * gamma * (1.0f / 127.0f);
    const float qs = 127.0f / gamma;
    uint2* dsth = reinterpret_cast<uint2*>(g_xqh) + (size_t)m * 1024;
#pragma unroll
    for (int i = 0; i < 4; i++) {
        int q0 = clampi(__float2int_rn(v[i].x * qs), -128, 127);
        int q1 = clampi(__float2int_rn(v[i].y * qs), -128, 127);
        int q2 = clampi(__float2int_rn(v[i].z * qs), -128, 127);
        int q3 = clampi(__float2int_rn(v[i].w * qs), -128, 127);
        uint2 h;
        h.x = pack_bf16((float)q0, (float)q1);
        h.y = pack_bf16((float)q2, (float)q3);
        dsth[t + 256 * i] = h;
    }
}

// ================= bf16 HMMA GEMM + per-row rescale ==========================
// D[m,n] = sum_k xq[m,k] * wq[n,k]  (exact: integers in bf16, fp32 accum)
// CTA tile 128x256, 8 warps of 64x64 (halves smem-read redundancy: the smem
// crossbar was the binding pipe at 64x32). BK=64 (128B rows), pad-144,
// 4-stage cp.async pipeline with wait_group 1 (guarantees chunks c AND c+1
// before the kk=3 next-chunk fragment prefetch), fragment double-buffering.
static constexpr int LDS_PADH = 144;
static constexpr int A_SZ   = 128 * LDS_PADH;        // 18432
static constexpr int B_SZ   = 256 * LDS_PADH;        // 36864
static constexpr int STAGEH = A_SZ + B_SZ;           // 55296
static constexpr int SMEMH  = 4 * STAGEH;            // 221184

__global__ void __launch_bounds__(256, 1) k_gemm_bf16(float* __restrict__ out) {
    extern __shared__ char smemraw[];
    const uint32_t sbase = smem_u32(smemraw);
    const int t = threadIdx.x;
    const int lane = t & 31, wid = t >> 5;
    const int warpM = wid >> 2;          // 0..1  -> 64-row M slab
    const int warpN = wid & 3;           // 0..3  -> 64-col N slab
    const int m0 = blockIdx.y * 128, n0 = blockIdx.x * 256;

    const char* gA = reinterpret_cast<const char*>(g_xqh) + (size_t)m0 * 8192;
    const char* gB = reinterpret_cast<const char*>(g_wqh) + (size_t)n0 * 8192;

    // loader: 2 threads per 128B row; A row lr, B rows lr and lr+128
    const int lr = t >> 1;               // 0..127
    const int lc = (t & 1) * 64;         // 0 or 64
    const char* pA = gA + (size_t)lr * 8192 + lc;
    const char* pB = gB + (size_t)lr * 8192 + lc;
    const uint32_t offA  = (uint32_t)(lr * LDS_PADH + lc);
    const uint32_t offB1 = (uint32_t)(A_SZ + lr * LDS_PADH + lc);
    const uint32_t offB2 = offB1 + 128 * LDS_PADH;

    const int xrow = (lane & 7) + ((lane >> 3) & 1) * 8;
    const int xcol = (lane >> 4) * 16;
    const uint32_t baseA = (uint32_t)((warpM * 64 + xrow) * LDS_PADH + xcol);
    const uint32_t baseB = (uint32_t)(A_SZ + (warpN * 64 + xrow) * LDS_PADH + xcol);

    float acc[4][8][4];
#pragma unroll
    for (int i = 0; i < 4; i++)
#pragma unroll
        for (int j = 0; j < 8; j++)
#pragma unroll
            for (int q = 0; q < 4; q++) acc[i][j][q] = 0.f;

    auto load_stage = [&](int s, int c) {
        const uint32_t dst = sbase + s * STAGEH;
        const char* sA = pA + (size_t)c * 128;
        const char* sB = pB + (size_t)c * 128;
#pragma unroll
        for (int i = 0; i < 4; i++) cp16(dst + offA  + i * 16, sA + i * 16);
#pragma unroll
        for (int i = 0; i < 4; i++) cp16(dst + offB1 + i * 16, sB + i * 16);
#pragma unroll
        for (int i = 0; i < 4; i++) cp16(dst + offB2 + i * 16, sB + (size_t)128 * 8192 + i * 16);
    };

    // fragment double buffers: a 2x16 regs, b 2x16 regs
    uint32_t a[2][4][4];
    uint32_t b[2][8][2];

    auto load_frags = [&](int buf, uint32_t st, int kk) {
#pragma unroll
        for (int i = 0; i < 4; i++)
            ldsm_x4(a[buf][i][0], a[buf][i][1], a[buf][i][2], a[buf][i][3],
                    st + baseA + i * (16 * LDS_PADH) + kk * 32);
#pragma unroll
        for (int j2 = 0; j2 < 4; j2++) {
            uint32_t q0, q1, q2, q3;
            ldsm_x4(q0, q1, q2, q3,
                    st + baseB + j2 * (16 * LDS_PADH) + kk * 32);
            b[buf][2 * j2][0] = q0; b[buf][2 * j2 + 1][0] = q1;
            b[buf][2 * j2][1] = q2; b[buf][2 * j2 + 1][1] = q3;
        }
    };

    // prologue: stages 0..2 as groups 0..2
#pragma unroll
    for (int c = 0; c < 3; c++) { load_stage(c, c); cp_commit(); }
    cp_wait1();          // groups 0,1 done -> chunks 0 and 1 resident
    __syncthreads();
    load_frags(0, sbase, 0);

    for (int c = 0; c < 64; c++) {
        // Top of chunk c: committed groups 0..c+2 (chunk g <- group g).
        // wait_group 1 -> pending <= 1 -> groups 0..c+1 done: chunk c (all kk)
        // and chunk c+1 (kk=3 prefetch target) are both guaranteed resident.
        // Stage (c+3)%4 being refilled == chunk c-1's stage; its last readers
        // finished during chunk c-1, strictly before this barrier.
        cp_wait1();
        __syncthreads();

        const int kn = c + 3;
        if (kn < 64) load_stage(kn & 3, kn);
        cp_commit();                 // uniform group count

        const uint32_t stC  = sbase + (c & 3) * STAGEH;
        const uint32_t stC1 = sbase + ((c + 1) & 3) * STAGEH;

#pragma unroll
        for (int kk = 0; kk < 4; kk++) {
            const int cur = kk & 1;
            const int nxt = cur ^ 1;
            if (kk < 3)        load_frags(nxt, stC, kk + 1);
            else if (c < 63)   load_frags(nxt, stC1, 0);
#pragma unroll
            for (int i = 0; i < 4; i++)
#pragma unroll
                for (int j = 0; j < 8; j++)
                    mma_bf16(acc[i][j], a[cur][i][0], a[cur][i][1],
                             a[cur][i][2], a[cur][i][3],
                             b[cur][j][0], b[cur][j][1]);
        }
    }

    // epilogue: scale by per-row alpha*gamma/127 and store fp32
    const int rq = lane >> 2;
    const int cq = (lane & 3) * 2;
    const int nwcol = n0 + warpN * 64 + cq;
#pragma unroll
    for (int i = 0; i < 4; i++) {
        const int row = m0 + warpM * 64 + i * 16 + rq;
        const float s0 = g_scales[row];
        const float s1 = g_scales[row + 8];
        float* o0 = out + (size_t)row * 4096 + nwcol;
        float* o1 = o0 + (size_t)8 * 4096;
#pragma unroll
        for (int j = 0; j < 8; j++) {
            float2 v0; v0.x = acc[i][j][0] * s0; v0.y = acc[i][j][1] * s0;
            *reinterpret_cast<float2*>(o0 + j * 8) = v0;
            float2 v1; v1.x = acc[i][j][2] * s1; v1.y = acc[i][j][3] * s1;
            *reinterpret_cast<float2*>(o1 + j * 8) = v1;
        }
    }
}

// ---------------- launch -----------------------------------------------------
extern "C" void kernel_launch(void* const* d_in, const int* in_sizes, int n_in,
                              void* d_out, int out_size) {
    (void)in_sizes; (void)n_in; (void)out_size;
    const float* x  = reinterpret_cast<const float*>(d_in[0]);
    const float* w  = reinterpret_cast<const float*>(d_in[1]);
    const float* nw = reinterpret_cast<const float*>(d_in[2]);
    float* y = reinterpret_cast<float*>(d_out);

    static bool attr_set = false;
    if (!attr_set) {
        cudaFuncSetAttribute(k_gemm_bf16, cudaFuncAttributeMaxDynamicSharedMemorySize, SMEMH);
        attr_set = true;
    }

    k_abs_partial<<<256, 256>>>(reinterpret_cast<const float4*>(w));
    k_quant_w<<<16384, 256>>>(reinterpret_cast<const float4*>(w));
    k_quant_x<<<4096, 256>>>(x, nw);
    k_gemm_bf16<<<dim3(16, 32), 256, SMEMH>>>(y);
}

// round 12
// speedup vs baseline: 1.4722x; 1.0992x over previous
#include <cuda_runtime.h>
#include <cuda_bf16.h>
#include <cstdint>

#define DINLINE __device__ __forceinline__

// ---------------- scratch (device globals; no runtime allocation) ----------
__device__ float g_partial[256];
__device__ float g_scales[4096];
__device__ float g_alpha_out;
__device__ __align__(128) __nv_bfloat16 g_wqh[16777216];  // W ternary bf16 [N,K]
__device__ __align__(128) __nv_bfloat16 g_xqh[16777216];  // x quant  bf16 [M,K]

// ---------------- PTX helpers (baseline ISA only) ---------------------------
DINLINE uint32_t smem_u32(const void* p) {
    uint32_t a;
    asm("{ .reg .u64 t; cvta.to.shared.u64 t, %1; cvt.u32.u64 %0, t; }"
        : "=r"(a) : "l"(p));
    return a;
}
DINLINE void cp16(uint32_t dst, const void* src) {
    asm volatile("cp.async.cg.shared.global [%0], [%1], 16;" :: "r"(dst), "l"(src));
}
DINLINE void cp_commit() { asm volatile("cp.async.commit_group;" ::: "memory"); }
DINLINE void cp_wait1()  { asm volatile("cp.async.wait_group 1;" ::: "memory"); }

DINLINE void ldsm_x4(uint32_t& r0, uint32_t& r1, uint32_t& r2, uint32_t& r3, uint32_t addr) {
    asm volatile("ldmatrix.sync.aligned.m8n8.x4.shared.b16 {%0,%1,%2,%3}, [%4];"
                 : "=r"(r0), "=r"(r1), "=r"(r2), "=r"(r3) : "r"(addr));
}
DINLINE void mma_bf16(float* c, uint32_t a0, uint32_t a1, uint32_t a2, uint32_t a3,
                      uint32_t b0, uint32_t b1) {
    asm volatile(
        "mma.sync.aligned.m16n8k16.row.col.f32.bf16.bf16.f32 "
        "{%0,%1,%2,%3}, {%4,%5,%6,%7}, {%8,%9}, {%0,%1,%2,%3};"
        : "+f"(c[0]), "+f"(c[1]), "+f"(c[2]), "+f"(c[3])
        : "r"(a0), "r"(a1), "r"(a2), "r"(a3), "r"(b0), "r"(b1));
}
DINLINE int clampi(int v, int lo, int hi) { return v < lo ? lo : (v > hi ? hi : v); }
DINLINE uint32_t pack_bf16(float a, float b) {
    __nv_bfloat162 h;
    h.x = __float2bfloat16(a);
    h.y = __float2bfloat16(b);
    return *reinterpret_cast<uint32_t*>(&h);
}

// ---------------- kernel 1: |W| partial sums ---------------------------------
__global__ void __launch_bounds__(256) k_abs_partial(const float4* __restrict__ w) {
    __shared__ float red[256];
    const int b = blockIdx.x, t = threadIdx.x;
    const float4* p = w + (size_t)b * 16384;
    float s = 0.f;
#pragma unroll 8
    for (int i = 0; i < 64; i++) {
        float4 v = p[t + 256 * i];
        s += fabsf(v.x) + fabsf(v.y) + fabsf(v.z) + fabsf(v.w);
    }
    red[t] = s; __syncthreads();
#pragma unroll
    for (int o = 128; o > 0; o >>= 1) { if (t < o) red[t] += red[t + o]; __syncthreads(); }
    if (t == 0) g_partial[b] = red[0];
}

// ---------------- kernel 2: finalize alpha + ternary quantize W -> bf16 -----
__global__ void __launch_bounds__(256) k_quant_w(const float4* __restrict__ w) {
    __shared__ float red[256];
    const int t = threadIdx.x;
    red[t] = g_partial[t]; __syncthreads();
#pragma unroll
    for (int o = 128; o > 0; o >>= 1) { if (t < o) red[t] += red[t + o]; __syncthreads(); }
    const float alpha = fmaxf(red[0] * (1.0f / 16777216.0f), 1e-10f);
    if (blockIdx.x == 0 && t == 0) g_alpha_out = alpha;
    const float inv_alpha = 1.0f / alpha;

    const int idx = blockIdx.x * 256 + t;          // float4 index, 4194304 total
    float4 v = w[idx];
    int q0 = clampi(__float2int_rn(v.x * inv_alpha), -1, 1);
    int q1 = clampi(__float2int_rn(v.y * inv_alpha), -1, 1);
    int q2 = clampi(__float2int_rn(v.z * inv_alpha), -1, 1);
    int q3 = clampi(__float2int_rn(v.w * inv_alpha), -1, 1);
    uint2 h;
    h.x = pack_bf16((float)q0, (float)q1);
    h.y = pack_bf16((float)q2, (float)q3);
    reinterpret_cast<uint2*>(g_wqh)[idx] = h;
}

// ---------------- kernel 3: RMSNorm + int8-grid quantize x -> bf16 ----------
__global__ void __launch_bounds__(256) k_quant_x(const float* __restrict__ x,
                                                 const float* __restrict__ nw) {
    __shared__ float red[256];
    const int m = blockIdx.x, t = threadIdx.x;
    const float4* xr = reinterpret_cast<const float4*>(x + (size_t)m * 4096);
    const float4* nwr = reinterpret_cast<const float4*>(nw);

    float4 v[4], g[4];
    float ss = 0.f;
#pragma unroll
    for (int i = 0; i < 4; i++) {
        v[i] = xr[t + 256 * i];
        g[i] = nwr[t + 256 * i];
        ss += v[i].x * v[i].x + v[i].y * v[i].y + v[i].z * v[i].z + v[i].w * v[i].w;
    }
    red[t] = ss; __syncthreads();
#pragma unroll
    for (int o = 128; o > 0; o >>= 1) { if (t < o) red[t] += red[t + o]; __syncthreads(); }
    const float rinv = 1.0f / sqrtf(red[0] * (1.0f / 4096.0f) + 1e-6f);
    __syncthreads();

    float mx = 0.f;
#pragma unroll
    for (int i = 0; i < 4; i++) {
        v[i].x *= rinv * g[i].x; v[i].y *= rinv * g[i].y;
        v[i].z *= rinv * g[i].z; v[i].w *= rinv * g[i].w;
        mx = fmaxf(mx, fmaxf(fmaxf(fabsf(v[i].x), fabsf(v[i].y)),
                             fmaxf(fabsf(v[i].z), fabsf(v[i].w))));
    }
    red[t] = mx; __syncthreads();
#pragma unroll
    for (int o = 128; o > 0; o >>= 1) { if (t < o) red[t] = fmaxf(red[t], red[t + o]); __syncthreads(); }
    const float gamma = fmaxf(red[0], 1e-10f);
    if (t == 0) g_scales[m] = g_alpha_out * gamma * (1.0f / 127.0f);
    const float qs = 127.0f / gamma;
    uint2* dsth = reinterpret_cast<uint2*>(g_xqh) + (size_t)m * 1024;
#pragma unroll
    for (int i = 0; i < 4; i++) {
        int q0 = clampi(__float2int_rn(v[i].x * qs), -128, 127);
        int q1 = clampi(__float2int_rn(v[i].y * qs), -128, 127);
        int q2 = clampi(__float2int_rn(v[i].z * qs), -128, 127);
        int q3 = clampi(__float2int_rn(v[i].w * qs), -128, 127);
        uint2 h;
        h.x = pack_bf16((float)q0, (float)q1);
        h.y = pack_bf16((float)q2, (float)q3);
        dsth[t + 256 * i] = h;
    }
}

// Tile numbering shared by both GEMM kernels: linear big-tile id T in [0,512),
// n0 = (T & 15) * 256, m0 = (T >> 4) * 128.  Big kernel does T in [0,444)
// (exactly 3 clean waves of 148); remainder kernel does T in [444,512) as
// 136 half tiles of 128x128 (one partial wave).
static constexpr int BIG_TILES = 444;

// ================= GEMM big: 128x256 tile, 8 warps of 64x64 (R11 body) ======
static constexpr int LDS_PADH = 144;
static constexpr int A_SZ   = 128 * LDS_PADH;        // 18432
static constexpr int B_SZ   = 256 * LDS_PADH;        // 36864
static constexpr int STAGEH = A_SZ + B_SZ;           // 55296
static constexpr int SMEMH  = 4 * STAGEH;            // 221184

__global__ void __launch_bounds__(256, 1) k_gemm_big(float* __restrict__ out) {
    extern __shared__ char smemraw[];
    const uint32_t sbase = smem_u32(smemraw);
    const int t = threadIdx.x;
    const int lane = t & 31, wid = t >> 5;
    const int warpM = wid >> 2;          // 0..1  -> 64-row M slab
    const int warpN = wid & 3;           // 0..3  -> 64-col N slab
    const int T = blockIdx.x;
    const int m0 = (T >> 4) * 128, n0 = (T & 15) * 256;

    const char* gA = reinterpret_cast<const char*>(g_xqh) + (size_t)m0 * 8192;
    const char* gB = reinterpret_cast<const char*>(g_wqh) + (size_t)n0 * 8192;

    const int lr = t >> 1;               // 0..127
    const int lc = (t & 1) * 64;         // 0 or 64
    const char* pA = gA + (size_t)lr * 8192 + lc;
    const char* pB = gB + (size_t)lr * 8192 + lc;
    const uint32_t offA  = (uint32_t)(lr * LDS_PADH + lc);
    const uint32_t offB1 = (uint32_t)(A_SZ + lr * LDS_PADH + lc);
    const uint32_t offB2 = offB1 + 128 * LDS_PADH;

    const int xrow = (lane & 7) + ((lane >> 3) & 1) * 8;
    const int xcol = (lane >> 4) * 16;
    const uint32_t baseA = (uint32_t)((warpM * 64 + xrow) * LDS_PADH + xcol);
    const uint32_t baseB = (uint32_t)(A_SZ + (warpN * 64 + xrow) * LDS_PADH + xcol);

    float acc[4][8][4];
#pragma unroll
    for (int i = 0; i < 4; i++)
#pragma unroll
        for (int j = 0; j < 8; j++)
#pragma unroll
            for (int q = 0; q < 4; q++) acc[i][j][q] = 0.f;

    auto load_stage = [&](int s, int c) {
        const uint32_t dst = sbase + s * STAGEH;
        const char* sA = pA + (size_t)c * 128;
        const char* sB = pB + (size_t)c * 128;
#pragma unroll
        for (int i = 0; i < 4; i++) cp16(dst + offA  + i * 16, sA + i * 16);
#pragma unroll
        for (int i = 0; i < 4; i++) cp16(dst + offB1 + i * 16, sB + i * 16);
#pragma unroll
        for (int i = 0; i < 4; i++) cp16(dst + offB2 + i * 16, sB + (size_t)128 * 8192 + i * 16);
    };

    uint32_t a[2][4][4];
    uint32_t b[2][8][2];

    auto load_frags = [&](int buf, uint32_t st, int kk) {
#pragma unroll
        for (int i = 0; i < 4; i++)
            ldsm_x4(a[buf][i][0], a[buf][i][1], a[buf][i][2], a[buf][i][3],
                    st + baseA + i * (16 * LDS_PADH) + kk * 32);
#pragma unroll
        for (int j2 = 0; j2 < 4; j2++) {
            uint32_t q0, q1, q2, q3;
            ldsm_x4(q0, q1, q2, q3,
                    st + baseB + j2 * (16 * LDS_PADH) + kk * 32);
            b[buf][2 * j2][0] = q0; b[buf][2 * j2 + 1][0] = q1;
            b[buf][2 * j2][1] = q2; b[buf][2 * j2 + 1][1] = q3;
        }
    };

#pragma unroll
    for (int c = 0; c < 3; c++) { load_stage(c, c); cp_commit(); }
    cp_wait1();
    __syncthreads();
    load_frags(0, sbase, 0);

    for (int c = 0; c < 64; c++) {
        cp_wait1();
        __syncthreads();

        const int kn = c + 3;
        if (kn < 64) load_stage(kn & 3, kn);
        cp_commit();

        const uint32_t stC  = sbase + (c & 3) * STAGEH;
        const uint32_t stC1 = sbase + ((c + 1) & 3) * STAGEH;

#pragma unroll
        for (int kk = 0; kk < 4; kk++) {
            const int cur = kk & 1;
            const int nxt = cur ^ 1;
            if (kk < 3)        load_frags(nxt, stC, kk + 1);
            else if (c < 63)   load_frags(nxt, stC1, 0);
#pragma unroll
            for (int i = 0; i < 4; i++)
#pragma unroll
                for (int j = 0; j < 8; j++)
                    mma_bf16(acc[i][j], a[cur][i][0], a[cur][i][1],
                             a[cur][i][2], a[cur][i][3],
                             b[cur][j][0], b[cur][j][1]);
        }
    }

    const int rq = lane >> 2;
    const int cq = (lane & 3) * 2;
    const int nwcol = n0 + warpN * 64 + cq;
#pragma unroll
    for (int i = 0; i < 4; i++) {
        const int row = m0 + warpM * 64 + i * 16 + rq;
        const float s0 = g_scales[row];
        const float s1 = g_scales[row + 8];
        float* o0 = out + (size_t)row * 4096 + nwcol;
        float* o1 = o0 + (size_t)8 * 4096;
#pragma unroll
        for (int j = 0; j < 8; j++) {
            float2 v0; v0.x = acc[i][j][0] * s0; v0.y = acc[i][j][1] * s0;
            *reinterpret_cast<float2*>(o0 + j * 8) = v0;
            float2 v1; v1.x = acc[i][j][2] * s1; v1.y = acc[i][j][3] * s1;
            *reinterpret_cast<float2*>(o1 + j * 8) = v1;
        }
    }
}

// ================= GEMM rem: 128x128 tile, 8 warps of 64x32 (R9 body) =======
static constexpr int A9_SZ   = 128 * LDS_PADH;       // 18432
static constexpr int STAGE9  = 2 * A9_SZ;            // 36864
static constexpr int SMEM9   = 4 * STAGE9;           // 147456

__global__ void __launch_bounds__(256, 1) k_gemm_rem(float* __restrict__ out) {
    extern __shared__ char smemraw[];
    const uint32_t sbase = smem_u32(smemraw);
    const int t = threadIdx.x;
    const int lane = t & 31, wid = t >> 5;
    const int warpM = wid >> 2, warpN = wid & 3;
    const int S = blockIdx.x;                        // 0..135
    const int T = BIG_TILES + (S >> 1);
    const int m0 = (T >> 4) * 128;
    const int n0 = (T & 15) * 256 + (S & 1) * 128;

    const char* gA = reinterpret_cast<const char*>(g_xqh) + (size_t)m0 * 8192;
    const char* gB = reinterpret_cast<const char*>(g_wqh) + (size_t)n0 * 8192;

    const int lr = t >> 1;
    const int lc = (t & 1) * 64;
    const char* pA = gA + (size_t)lr * 8192 + lc;
    const char* pB = gB + (size_t)lr * 8192 + lc;
    const uint32_t offA = (uint32_t)(lr * LDS_PADH + lc);
    const uint32_t offB = offA + A9_SZ;

    const int xrow = (lane & 7) + ((lane >> 3) & 1) * 8;
    const int xcol = (lane >> 4) * 16;
    const uint32_t baseA = (uint32_t)((warpM * 64 + xrow) * LDS_PADH + xcol);
    const uint32_t baseB = (uint32_t)(A9_SZ + (warpN * 32 + xrow) * LDS_PADH + xcol);

    float acc[4][4][4];
#pragma unroll
    for (int i = 0; i < 4; i++)
#pragma unroll
        for (int j = 0; j < 4; j++)
#pragma unroll
            for (int q = 0; q < 4; q++) acc[i][j][q] = 0.f;

    auto load_stage = [&](int s, int c) {
        const uint32_t dst = sbase + s * STAGE9;
        const char* sA = pA + (size_t)c * 128;
        const char* sB = pB + (size_t)c * 128;
#pragma unroll
        for (int i = 0; i < 4; i++) {
            cp16(dst + offA + i * 16, sA + i * 16);
            cp16(dst + offB + i * 16, sB + i * 16);
        }
    };

    uint32_t a[2][4][4];
    uint32_t b[2][4][2];

    auto load_frags = [&](int buf, uint32_t st, int kk) {
#pragma unroll
        for (int i = 0; i < 4; i++)
            ldsm_x4(a[buf][i][0], a[buf][i][1], a[buf][i][2], a[buf][i][3],
                    st + baseA + i * (16 * LDS_PADH) + kk * 32);
#pragma unroll
        for (int j2 = 0; j2 < 2; j2++) {
            uint32_t q0, q1, q2, q3;
            ldsm_x4(q0, q1, q2, q3,
                    st + baseB + j2 * (16 * LDS_PADH) + kk * 32);
            b[buf][2 * j2][0] = q0; b[buf][2 * j2 + 1][0] = q1;
            b[buf][2 * j2][1] = q2; b[buf][2 * j2 + 1][1] = q3;
        }
    };

#pragma unroll
    for (int c = 0; c < 3; c++) { load_stage(c, c); cp_commit(); }
    cp_wait1();
    __syncthreads();
    load_frags(0, sbase, 0);

    for (int c = 0; c < 64; c++) {
        cp_wait1();
        __syncthreads();

        const int kn = c + 3;
        if (kn < 64) load_stage(kn & 3, kn);
        cp_commit();

        const uint32_t stC  = sbase + (c & 3) * STAGE9;
        const uint32_t stC1 = sbase + ((c + 1) & 3) * STAGE9;

#pragma unroll
        for (int kk = 0; kk < 4; kk++) {
            const int cur = kk & 1;
            const int nxt = cur ^ 1;
            if (kk < 3)        load_frags(nxt, stC, kk + 1);
            else if (c < 63)   load_frags(nxt, stC1, 0);
#pragma unroll
            for (int i = 0; i < 4; i++)
#pragma unroll
                for (int j = 0; j < 4; j++)
                    mma_bf16(acc[i][j], a[cur][i][0], a[cur][i][1],
                             a[cur][i][2], a[cur][i][3],
                             b[cur][j][0], b[cur][j][1]);
        }
    }

    const int rq = lane >> 2;
    const int cq = (lane & 3) * 2;
    const int nwcol = n0 + warpN * 32 + cq;
#pragma unroll
    for (int i = 0; i < 4; i++) {
        const int row = m0 + warpM * 64 + i * 16 + rq;
        const float s0 = g_scales[row];
        const float s1 = g_scales[row + 8];
        float* o0 = out + (size_t)row * 4096 + nwcol;
        float* o1 = o0 + (size_t)8 * 4096;
#pragma unroll
        for (int j = 0; j < 4; j++) {
            float2 v0; v0.x = acc[i][j][0] * s0; v0.y = acc[i][j][1] * s0;
            *reinterpret_cast<float2*>(o0 + j * 8) = v0;
            float2 v1; v1.x = acc[i][j][2] * s1; v1.y = acc[i][j][3] * s1;
            *reinterpret_cast<float2*>(o1 + j * 8) = v1;
        }
    }
}

// ---------------- launch -----------------------------------------------------
extern "C" void kernel_launch(void* const* d_in, const int* in_sizes, int n_in,
                              void* d_out, int out_size) {
    (void)in_sizes; (void)n_in; (void)out_size;
    const float* x  = reinterpret_cast<const float*>(d_in[0]);
    const float* w  = reinterpret_cast<const float*>(d_in[1]);
    const float* nw = reinterpret_cast<const float*>(d_in[2]);
    float* y = reinterpret_cast<float*>(d_out);

    static bool attr_set = false;
    if (!attr_set) {
        cudaFuncSetAttribute(k_gemm_big, cudaFuncAttributeMaxDynamicSharedMemorySize, SMEMH);
        cudaFuncSetAttribute(k_gemm_rem, cudaFuncAttributeMaxDynamicSharedMemorySize, SMEM9);
        attr_set = true;
    }

    k_abs_partial<<<256, 256>>>(reinterpret_cast<const float4*>(w));
    k_quant_w<<<16384, 256>>>(reinterpret_cast<const float4*>(w));
    k_quant_x<<<4096, 256>>>(x, nw);
    k_gemm_big<<<BIG_TILES, 256, SMEMH>>>(y);        // 444 tiles = 3 clean waves
    k_gemm_rem<<<136, 256, SMEM9>>>(y);              // 68 tiles as 136 halves
}